// round 7
// baseline (speedup 1.0000x reference)
#include <cuda_runtime.h>
#include <cuda_fp16.h>
#include <cstdint>

// Problem constants (fixed shapes for this problem instance)
#define NODES   50000
#define EDGES   800000
#define INF     512
#define OUTF    512
#define HEADS   8
#define NBASES  4
#define FHD     64          // OUTF/HEADS
#define AGGC    256         // NBASES*FHD
#define WCOMB   32          // HEADS*NBASES
#define NCAT    800         // 256 + 32 + 512 concatenated GEMM output cols
#define LNEPS   1e-5f

// ---------- device scratch (static allocation; no cudaMalloc allowed) ----------
__device__ float    g_wcatT[(size_t)NCAT * INF];       // transposed concat weights [800,512]
__device__ float    g_cat[(size_t)NODES * NCAT];       // x @ Wcat  [N,800]  (~160MB)
__device__ uint32_t g_bases_h[(size_t)NODES * 128];    // bases as half2 [N,128] (~25.6MB, L2-resident)
__device__ float    g_agg[(size_t)NODES * AGGC];       // symnorm aggregation [N,256] (~51MB)
__device__ float    g_dinv[NODES];
__device__ int      g_deg[NODES];
__device__ int      g_rowptr[NODES + 1];
__device__ int      g_cursor[NODES];
__device__ int      g_esrc[EDGES];                     // src ids sorted by dst
__device__ float    g_enrm[EDGES];                     // per-edge norm, same order

// ---------- zero deg ----------
__global__ void zerodeg_kernel(int n) {
    int i = blockIdx.x * blockDim.x + threadIdx.x;
    if (i < n) g_deg[i] = 0;
}

// ---------- concat + transpose weights into g_wcatT[c][k] ----------
__global__ void concatw_kernel(const float* __restrict__ Wb,
                               const float* __restrict__ Wc,
                               const float* __restrict__ Wr) {
    int i = blockIdx.x * blockDim.x + threadIdx.x;
    if (i >= INF * NCAT) return;
    int k = i & (INF - 1);       // fastest -> coalesced reads of Wb/Wc/Wr rows
    int c = i >> 9;
    float v;
    if (c < AGGC)              v = Wb[k * AGGC + c];
    else if (c < AGGC + WCOMB) v = Wc[k * WCOMB + (c - AGGC)];
    else                       v = Wr[k * OUTF + (c - AGGC - WCOMB)];
    g_wcatT[(size_t)c * INF + k] = v;
}

// ---------- degree count (dst occurrences) ----------
__global__ void deg_kernel(const int* __restrict__ ei, int E) {
    int i = blockIdx.x * blockDim.x + threadIdx.x;
    if (i < E) atomicAdd(&g_deg[ei[E + i]], 1);
}

__global__ void dinv_kernel(int n) {
    int i = blockIdx.x * blockDim.x + threadIdx.x;
    if (i < n) g_dinv[i] = rsqrtf((float)(g_deg[i] + 1));  // +1 self loop
}

// ---------- single-block exclusive scan of deg -> rowptr, cursor ----------
__global__ __launch_bounds__(1024)
void scan_kernel(int n, int E) {
    __shared__ int wsum[32];
    const int tid   = threadIdx.x;
    const int chunk = (n + 1023) >> 10;
    const int start = tid * chunk;
    const int end   = min(start + chunk, n);
    int sum = 0;
    for (int i = start; i < end; i++) sum += g_deg[i];
    const int lane = tid & 31, wid = tid >> 5;
    int v = sum;
#pragma unroll
    for (int o = 1; o < 32; o <<= 1) {
        int t = __shfl_up_sync(0xffffffffu, v, o);
        if (lane >= o) v += t;
    }
    if (lane == 31) wsum[wid] = v;
    __syncthreads();
    if (wid == 0) {
        int w = wsum[lane];
#pragma unroll
        for (int o = 1; o < 32; o <<= 1) {
            int t = __shfl_up_sync(0xffffffffu, w, o);
            if (lane >= o) w += t;
        }
        wsum[lane] = w;
    }
    __syncthreads();
    int off = v - sum + (wid ? wsum[wid - 1] : 0);
    for (int i = start; i < end; i++) {
        g_rowptr[i] = off;
        g_cursor[i] = off;
        off += g_deg[i];
    }
    if (tid == 0) g_rowptr[n] = E;
}

// ---------- fill CSR: edges bucketed by dst, norm precomputed ----------
__global__ void fill_kernel(const int* __restrict__ ei, int E) {
    int i = blockIdx.x * blockDim.x + threadIdx.x;
    if (i >= E) return;
    int s = ei[i], d = ei[E + i];
    int pos = atomicAdd(&g_cursor[d], 1);
    g_esrc[pos] = s;
    g_enrm[pos] = g_dinv[s] * g_dinv[d];
}

// ---------- FP16 tensor-core GEMM: g_cat[M,800] = x[M,512] @ W[512,800] ----------
__device__ __forceinline__ void mma_f16(float* d, const uint32_t* a, const uint32_t* b) {
    asm volatile("mma.sync.aligned.m16n8k16.row.col.f32.f16.f16.f32 "
                 "{%0,%1,%2,%3},{%4,%5,%6,%7},{%8,%9},{%0,%1,%2,%3};"
                 : "+f"(d[0]), "+f"(d[1]), "+f"(d[2]), "+f"(d[3])
                 : "r"(a[0]), "r"(a[1]), "r"(a[2]), "r"(a[3]),
                   "r"(b[0]), "r"(b[1]));
}

__device__ __forceinline__ uint32_t pack_h2(float lo, float hi) {
    __half2 h = __floats2half2_rn(lo, hi);
    return *reinterpret_cast<uint32_t*>(&h);
}

#define GBM 128
#define GBN 128
#define GBK 32
#define HP  20    // row pitch in words (16 half2 used + 4 pad)

__global__ __launch_bounds__(256, 2)
void f16gemm_kernel(const float* __restrict__ A, int M) {
    __shared__ uint32_t As[GBM][HP];   // [m][kpair]
    __shared__ uint32_t Bs[GBN][HP];   // [n][kpair]
    const int t    = threadIdx.x;
    const int wid  = t >> 5;
    const int lane = t & 31;
    const int wm   = wid & 3;          // 0..3 -> 32-row stripes
    const int wn   = wid >> 2;         // 0..1 -> 64-col stripes
    const int lr   = lane >> 2;        // groupID (0..7)
    const int lc   = lane & 3;         // threadID_in_group (0..3)
    const int m0   = blockIdx.y * GBM;
    const int n0   = blockIdx.x * GBN;

    float acc[2][8][4];
#pragma unroll
    for (int mt = 0; mt < 2; mt++)
#pragma unroll
        for (int nt = 0; nt < 8; nt++)
#pragma unroll
            for (int r = 0; r < 4; r++) acc[mt][nt][r] = 0.f;

    float4 pa[2][2], pb[2][2];

    auto loadA = [&](int kt) {
#pragma unroll
        for (int i = 0; i < 2; i++) {
            int f   = t + i * 256;
            int row = f >> 2;
            int q4  = (f & 3) * 4;
            int gr  = m0 + row;
            const float* src = A + (size_t)gr * INF + kt + q4 * 2;
            if (gr < M) {
                pa[i][0] = *reinterpret_cast<const float4*>(src);
                pa[i][1] = *reinterpret_cast<const float4*>(src + 4);
            } else {
                pa[i][0] = pa[i][1] = make_float4(0.f, 0.f, 0.f, 0.f);
            }
        }
    };
    auto loadB = [&](int kt) {
#pragma unroll
        for (int i = 0; i < 2; i++) {
            int f   = t + i * 256;
            int row = f >> 2;
            int q4  = (f & 3) * 4;
            int gn  = n0 + row;
            const float* src = g_wcatT + (size_t)gn * INF + kt + q4 * 2;
            if (gn < NCAT) {
                pb[i][0] = *reinterpret_cast<const float4*>(src);
                pb[i][1] = *reinterpret_cast<const float4*>(src + 4);
            } else {
                pb[i][0] = pb[i][1] = make_float4(0.f, 0.f, 0.f, 0.f);
            }
        }
    };

    loadA(0);
    loadB(0);

    for (int kt = 0; kt < INF; kt += GBK) {
#pragma unroll
        for (int i = 0; i < 2; i++) {
            int f   = t + i * 256;
            int row = f >> 2;
            int q4  = (f & 3) * 4;
            uint4 ua = make_uint4(pack_h2(pa[i][0].x, pa[i][0].y),
                                  pack_h2(pa[i][0].z, pa[i][0].w),
                                  pack_h2(pa[i][1].x, pa[i][1].y),
                                  pack_h2(pa[i][1].z, pa[i][1].w));
            *reinterpret_cast<uint4*>(&As[row][q4]) = ua;
            uint4 ub = make_uint4(pack_h2(pb[i][0].x, pb[i][0].y),
                                  pack_h2(pb[i][0].z, pb[i][0].w),
                                  pack_h2(pb[i][1].x, pb[i][1].y),
                                  pack_h2(pb[i][1].z, pb[i][1].w));
            *reinterpret_cast<uint4*>(&Bs[row][q4]) = ub;
        }
        __syncthreads();

        if (kt + GBK < INF) {
            loadA(kt + GBK);
            loadB(kt + GBK);
        }

#pragma unroll
        for (int s = 0; s < 2; s++) {
            const int ko = s * 8;
            uint32_t af[2][4];
#pragma unroll
            for (int mt = 0; mt < 2; mt++) {
                int r0 = wm * 32 + mt * 16 + lr;
                af[mt][0] = As[r0][ko + lc];
                af[mt][1] = As[r0 + 8][ko + lc];
                af[mt][2] = As[r0][ko + lc + 4];
                af[mt][3] = As[r0 + 8][ko + lc + 4];
            }
#pragma unroll
            for (int nt = 0; nt < 8; nt++) {
                int col = wn * 64 + nt * 8 + lr;
                uint32_t bf[2];
                bf[0] = Bs[col][ko + lc];
                bf[1] = Bs[col][ko + lc + 4];
#pragma unroll
                for (int mt = 0; mt < 2; mt++)
                    mma_f16(acc[mt][nt], af[mt], bf);
            }
        }
        __syncthreads();
    }

    // store fp32 to g_cat; bases block (cols<256) additionally as half2
#pragma unroll
    for (int mt = 0; mt < 2; mt++) {
#pragma unroll
        for (int nt = 0; nt < 8; nt++) {
            int row = m0 + wm * 32 + mt * 16 + lr;
            int col = n0 + wn * 64 + nt * 8 + 2 * lc;
            if (col < NCAT) {
                if (row < M) {
                    float2 v = make_float2(acc[mt][nt][0], acc[mt][nt][1]);
                    *reinterpret_cast<float2*>(g_cat + (size_t)row * NCAT + col) = v;
                    if (col < AGGC)
                        g_bases_h[(size_t)row * 128 + (col >> 1)] = pack_h2(v.x, v.y);
                }
                if (row + 8 < M) {
                    float2 v = make_float2(acc[mt][nt][2], acc[mt][nt][3]);
                    *reinterpret_cast<float2*>(g_cat + (size_t)(row + 8) * NCAT + col) = v;
                    if (col < AGGC)
                        g_bases_h[(size_t)(row + 8) * 128 + (col >> 1)] = pack_h2(v.x, v.y);
                }
            }
        }
    }
}

// ---------- gather: agg[v] = sum_{e in CSR row v} bases_h[src(e)] * nrm(e) ----------
// one block (128 threads) per dst node; register accumulation, no atomics.
__global__ __launch_bounds__(128)
void gather_kernel() {
    const int v   = blockIdx.x;
    const int tid = threadIdx.x;
    const int beg = g_rowptr[v];
    const int end = g_rowptr[v + 1];
    float2 acc = make_float2(0.f, 0.f);

    int   s_cur = 0;
    float n_cur = 0.f;
    if (beg < end) { s_cur = __ldg(&g_esrc[beg]); n_cur = __ldg(&g_enrm[beg]); }
#pragma unroll 4
    for (int e = beg; e < end; e++) {
        int   s_nx = 0;
        float n_nx = 0.f;
        if (e + 1 < end) { s_nx = __ldg(&g_esrc[e + 1]); n_nx = __ldg(&g_enrm[e + 1]); }
        uint32_t h = __ldg(&g_bases_h[(size_t)s_cur * 128 + tid]);
        __half2 hh = *reinterpret_cast<__half2*>(&h);
        float2 f = __half22float2(hh);
        acc.x = fmaf(f.x, n_cur, acc.x);
        acc.y = fmaf(f.y, n_cur, acc.y);
        s_cur = s_nx;
        n_cur = n_nx;
    }
    *reinterpret_cast<float2*>(&g_agg[(size_t)v * AGGC + 2 * tid]) = acc;
}

// ---------- combine: einsum + biases + residual + LayerNorm + ReLU ----------
__global__ __launch_bounds__(128)
void combine_kernel(const float* __restrict__ b_comb,
                    const float* __restrict__ conv_bias,
                    const float* __restrict__ b_res,
                    const float* __restrict__ gamma,
                    const float* __restrict__ beta,
                    float* __restrict__ out) {
    int v = blockIdx.x;
    int tid = threadIdx.x;
    __shared__ float sagg[AGGC];
    __shared__ float sw[WCOMB];
    __shared__ float red[8];

    float d = g_dinv[v];
    float d2 = d * d;
    const float* oc = g_cat + (size_t)v * NCAT;
    const float* ag = g_agg + (size_t)v * AGGC;

    // agg row + self-loop term (fp32 bases from g_cat)
#pragma unroll
    for (int j = 0; j < 2; j++) {
        int i = tid + j * 128;
        sagg[i] = ag[i] + oc[i] * d2;
    }
    if (tid < WCOMB) sw[tid] = oc[AGGC + tid] + b_comb[tid];
    __syncthreads();

    float val[4];
    float s = 0.f, sq = 0.f;
#pragma unroll
    for (int j = 0; j < 4; j++) {
        int c = tid + j * 128;
        int h = c >> 6, f = c & 63;
        const float* wv = &sw[h * 4];
        float a = wv[0] * sagg[f]
                + wv[1] * sagg[64 + f]
                + wv[2] * sagg[128 + f]
                + wv[3] * sagg[192 + f];
        a += conv_bias[c] + oc[AGGC + WCOMB + c] + b_res[c];
        val[j] = a;
        s += a;
        sq += a * a;
    }
#pragma unroll
    for (int o = 16; o > 0; o >>= 1) {
        s  += __shfl_xor_sync(0xffffffffu, s, o);
        sq += __shfl_xor_sync(0xffffffffu, sq, o);
    }
    if ((tid & 31) == 0) { red[tid >> 5] = s; red[4 + (tid >> 5)] = sq; }
    __syncthreads();
    s  = red[0] + red[1] + red[2] + red[3];
    sq = red[4] + red[5] + red[6] + red[7];
    float mean = s * (1.f / OUTF);
    float var  = sq * (1.f / OUTF) - mean * mean;
    float rstd = rsqrtf(var + LNEPS);
#pragma unroll
    for (int j = 0; j < 4; j++) {
        int c = tid + j * 128;
        float o = (val[j] - mean) * rstd * gamma[c] + beta[c];
        out[(size_t)v * OUTF + c] = fmaxf(o, 0.f);
    }
}

extern "C" void kernel_launch(void* const* d_in, const int* in_sizes, int n_in,
                              void* d_out, int out_size) {
    const float* x     = (const float*)d_in[0];
    const int*   ei    = (const int*)  d_in[1];
    const float* Wb    = (const float*)d_in[2];
    const float* Wc    = (const float*)d_in[3];
    const float* bcomb = (const float*)d_in[4];
    const float* cbias = (const float*)d_in[5];
    const float* Wr    = (const float*)d_in[6];
    const float* bres  = (const float*)d_in[7];
    const float* gamma = (const float*)d_in[8];
    const float* beta  = (const float*)d_in[9];
    float* out = (float*)d_out;

    const int N = in_sizes[0] / INF;
    const int E = in_sizes[1] / 2;

    // graph prep: deg -> dinv -> rowptr -> csr fill
    zerodeg_kernel<<<(N + 255) / 256, 256>>>(N);
    concatw_kernel<<<(INF * NCAT + 255) / 256, 256>>>(Wb, Wc, Wr);
    deg_kernel<<<(E + 255) / 256, 256>>>(ei, E);
    dinv_kernel<<<(N + 255) / 256, 256>>>(N);
    scan_kernel<<<1, 1024>>>(N, E);
    fill_kernel<<<(E + 255) / 256, 256>>>(ei, E);
    // fused GEMM (FP16 tensor cores, fp32 accum): g_cat = x @ W (+ fp16 bases copy)
    {
        dim3 grid((NCAT + GBN - 1) / GBN, (N + GBM - 1) / GBM);
        f16gemm_kernel<<<grid, 256>>>(x, N);
    }
    // atomic-free CSR gather
    gather_kernel<<<N, 128>>>();
    // combine + LayerNorm + ReLU
    combine_kernel<<<N, 128>>>(bcomb, cbias, bres, gamma, beta, out);
}

// round 8
// speedup vs baseline: 1.0448x; 1.0448x over previous
#include <cuda_runtime.h>
#include <cuda_fp16.h>
#include <cstdint>

// Problem constants (fixed shapes for this problem instance)
#define NODES   50000
#define EDGES   800000
#define INF     512
#define OUTF    512
#define HEADS   8
#define NBASES  4
#define FHD     64          // OUTF/HEADS
#define AGGC    256         // NBASES*FHD
#define WCOMB   32          // HEADS*NBASES
#define NCAT    800         // 256 + 32 + 512 concatenated GEMM output cols
#define LNEPS   1e-5f

// ---------- device scratch (static allocation; no cudaMalloc allowed) ----------
__device__ float g_wcatT[(size_t)NCAT * INF];        // transposed concat weights [800,512]
__device__ float g_cat[(size_t)NODES * NCAT];        // x @ Wcat  [N,800]  (~160MB)
__device__ float g_agg[(size_t)NODES * AGGC];        // symnorm aggregation [N,256] (~51MB)
__device__ float g_dinv[NODES];
__device__ int   g_deg[NODES];

// ---------- zero agg + deg ----------
__global__ void zero_kernel(int nAgg4, int nDeg) {
    int i = blockIdx.x * blockDim.x + threadIdx.x;
    if (i < nAgg4) reinterpret_cast<float4*>(g_agg)[i] = make_float4(0.f, 0.f, 0.f, 0.f);
    if (i < nDeg)  g_deg[i] = 0;
}

// ---------- concat + transpose weights into g_wcatT[c][k] ----------
__global__ void concatw_kernel(const float* __restrict__ Wb,
                               const float* __restrict__ Wc,
                               const float* __restrict__ Wr) {
    int i = blockIdx.x * blockDim.x + threadIdx.x;
    if (i >= INF * NCAT) return;
    int k = i & (INF - 1);       // fastest -> coalesced reads of Wb/Wc/Wr rows
    int c = i >> 9;
    float v;
    if (c < AGGC)              v = Wb[k * AGGC + c];
    else if (c < AGGC + WCOMB) v = Wc[k * WCOMB + (c - AGGC)];
    else                       v = Wr[k * OUTF + (c - AGGC - WCOMB)];
    g_wcatT[(size_t)c * INF + k] = v;
}

// ---------- degree count (dst occurrences) ----------
__global__ void deg_kernel(const int* __restrict__ ei, int E) {
    int i = blockIdx.x * blockDim.x + threadIdx.x;
    if (i < E) atomicAdd(&g_deg[ei[E + i]], 1);
}

__global__ void dinv_kernel(int n) {
    int i = blockIdx.x * blockDim.x + threadIdx.x;
    if (i < n) g_dinv[i] = rsqrtf((float)(g_deg[i] + 1));  // +1 self loop
}

// ---------- FP16 tensor-core GEMM: g_cat[M,800] = x[M,512] @ W[512,800] ----------
// 128x128 block tile, BK=32, 256 threads (8 warps 4m x 2n), warp tile 32x64.
// DOUBLE-BUFFERED smem: one __syncthreads per k-slab; staging of slab k+1
// overlaps other warps' MMA of slab k. Fragment/staging patterns identical
// to the proven single-buffer version (pitch 20 words, conflict-free).
__device__ __forceinline__ void mma_f16(float* d, const uint32_t* a, const uint32_t* b) {
    asm volatile("mma.sync.aligned.m16n8k16.row.col.f32.f16.f16.f32 "
                 "{%0,%1,%2,%3},{%4,%5,%6,%7},{%8,%9},{%0,%1,%2,%3};"
                 : "+f"(d[0]), "+f"(d[1]), "+f"(d[2]), "+f"(d[3])
                 : "r"(a[0]), "r"(a[1]), "r"(a[2]), "r"(a[3]),
                   "r"(b[0]), "r"(b[1]));
}

__device__ __forceinline__ uint32_t pack_h2(float lo, float hi) {
    __half2 h = __floats2half2_rn(lo, hi);
    return *reinterpret_cast<uint32_t*>(&h);
}

#define GBM 128
#define GBN 128
#define GBK 32
#define HP  20    // row pitch in words (16 half2 used + 4 pad)

__global__ __launch_bounds__(256, 2)
void f16gemm_kernel(const float* __restrict__ A, int M) {
    __shared__ uint32_t As[2][GBM][HP];   // [stage][m][kpair]
    __shared__ uint32_t Bs[2][GBN][HP];   // [stage][n][kpair]
    const int t    = threadIdx.x;
    const int wid  = t >> 5;
    const int lane = t & 31;
    const int wm   = wid & 3;          // 0..3 -> 32-row stripes
    const int wn   = wid >> 2;         // 0..1 -> 64-col stripes
    const int lr   = lane >> 2;        // groupID (0..7)
    const int lc   = lane & 3;         // threadID_in_group (0..3)
    const int m0   = blockIdx.y * GBM;
    const int n0   = blockIdx.x * GBN;

    float acc[2][8][4];
#pragma unroll
    for (int mt = 0; mt < 2; mt++)
#pragma unroll
        for (int nt = 0; nt < 8; nt++)
#pragma unroll
            for (int r = 0; r < 4; r++) acc[mt][nt][r] = 0.f;

    float4 pa[2][2], pb[2][2];

    auto loadA = [&](int kt) {
#pragma unroll
        for (int i = 0; i < 2; i++) {
            int f   = t + i * 256;
            int row = f >> 2;
            int q4  = (f & 3) * 4;
            int gr  = m0 + row;
            const float* src = A + (size_t)gr * INF + kt + q4 * 2;
            if (gr < M) {
                pa[i][0] = *reinterpret_cast<const float4*>(src);
                pa[i][1] = *reinterpret_cast<const float4*>(src + 4);
            } else {
                pa[i][0] = pa[i][1] = make_float4(0.f, 0.f, 0.f, 0.f);
            }
        }
    };
    auto loadB = [&](int kt) {
#pragma unroll
        for (int i = 0; i < 2; i++) {
            int f   = t + i * 256;
            int row = f >> 2;
            int q4  = (f & 3) * 4;
            int gn  = n0 + row;
            const float* src = g_wcatT + (size_t)gn * INF + kt + q4 * 2;
            if (gn < NCAT) {
                pb[i][0] = *reinterpret_cast<const float4*>(src);
                pb[i][1] = *reinterpret_cast<const float4*>(src + 4);
            } else {
                pb[i][0] = pb[i][1] = make_float4(0.f, 0.f, 0.f, 0.f);
            }
        }
    };

    loadA(0);
    loadB(0);
    int buf = 0;

    for (int kt = 0; kt < INF; kt += GBK) {
        // stage prefetched regs -> smem[buf]
#pragma unroll
        for (int i = 0; i < 2; i++) {
            int f   = t + i * 256;
            int row = f >> 2;
            int q4  = (f & 3) * 4;
            uint4 ua = make_uint4(pack_h2(pa[i][0].x, pa[i][0].y),
                                  pack_h2(pa[i][0].z, pa[i][0].w),
                                  pack_h2(pa[i][1].x, pa[i][1].y),
                                  pack_h2(pa[i][1].z, pa[i][1].w));
            *reinterpret_cast<uint4*>(&As[buf][row][q4]) = ua;
            uint4 ub = make_uint4(pack_h2(pb[i][0].x, pb[i][0].y),
                                  pack_h2(pb[i][0].z, pb[i][0].w),
                                  pack_h2(pb[i][1].x, pb[i][1].y),
                                  pack_h2(pb[i][1].z, pb[i][1].w));
            *reinterpret_cast<uint4*>(&Bs[buf][row][q4]) = ub;
        }
        __syncthreads();   // the ONLY sync per slab

        if (kt + GBK < INF) {
            loadA(kt + GBK);
            loadB(kt + GBK);
        }

        // compute from smem[buf]
#pragma unroll
        for (int s = 0; s < 2; s++) {
            const int ko = s * 8;
            uint32_t af[2][4];
#pragma unroll
            for (int mt = 0; mt < 2; mt++) {
                int r0 = wm * 32 + mt * 16 + lr;
                af[mt][0] = As[buf][r0][ko + lc];
                af[mt][1] = As[buf][r0 + 8][ko + lc];
                af[mt][2] = As[buf][r0][ko + lc + 4];
                af[mt][3] = As[buf][r0 + 8][ko + lc + 4];
            }
#pragma unroll
            for (int nt = 0; nt < 8; nt++) {
                int col = wn * 64 + nt * 8 + lr;
                uint32_t bf[2];
                bf[0] = Bs[buf][col][ko + lc];
                bf[1] = Bs[buf][col][ko + lc + 4];
#pragma unroll
                for (int mt = 0; mt < 2; mt++)
                    mma_f16(acc[mt][nt], af[mt], bf);
            }
        }
        buf ^= 1;   // next slab stages into the other buffer; no second sync
    }

    // store
#pragma unroll
    for (int mt = 0; mt < 2; mt++) {
#pragma unroll
        for (int nt = 0; nt < 8; nt++) {
            int row = m0 + wm * 32 + mt * 16 + lr;
            int col = n0 + wn * 64 + nt * 8 + 2 * lc;
            if (col < NCAT) {
                if (row < M) {
                    float2 v = make_float2(acc[mt][nt][0], acc[mt][nt][1]);
                    *reinterpret_cast<float2*>(g_cat + (size_t)row * NCAT + col) = v;
                }
                if (row + 8 < M) {
                    float2 v = make_float2(acc[mt][nt][2], acc[mt][nt][3]);
                    *reinterpret_cast<float2*>(g_cat + (size_t)(row + 8) * NCAT + col) = v;
                }
            }
        }
    }
}

// ---------- edge scatter: agg[dst] += bases[src] * dinv[src]*dinv[dst] ----------
__device__ __forceinline__ void red_add_v4(float* addr, float a, float b, float c, float d) {
    asm volatile("red.global.add.v4.f32 [%0], {%1, %2, %3, %4};"
                 :: "l"(addr), "f"(a), "f"(b), "f"(c), "f"(d) : "memory");
}

__global__ void scatter_kernel(const int* __restrict__ ei, int E) {
    int w = (blockIdx.x * blockDim.x + threadIdx.x) >> 5;
    if (w >= E) return;
    int lane = threadIdx.x & 31;
    int src = __ldg(ei + w);
    int dst = __ldg(ei + E + w);
    float nrm = __ldg(g_dinv + src) * __ldg(g_dinv + dst);
    const float4* brow = reinterpret_cast<const float4*>(g_cat + (size_t)src * NCAT);
    float* arow = g_agg + (size_t)dst * AGGC;
#pragma unroll
    for (int i = 0; i < 2; i++) {
        int q = lane + i * 32;
        float4 v = __ldg(brow + q);
        red_add_v4(arow + q * 4, v.x * nrm, v.y * nrm, v.z * nrm, v.w * nrm);
    }
}

// ---------- combine: einsum + biases + residual + LayerNorm + ReLU ----------
__global__ __launch_bounds__(128)
void combine_kernel(const float* __restrict__ b_comb,
                    const float* __restrict__ conv_bias,
                    const float* __restrict__ b_res,
                    const float* __restrict__ gamma,
                    const float* __restrict__ beta,
                    float* __restrict__ out) {
    int v = blockIdx.x;
    int tid = threadIdx.x;
    __shared__ float sagg[AGGC];
    __shared__ float sw[WCOMB];
    __shared__ float red[8];

    float d = g_dinv[v];
    float d2 = d * d;
    const float* oc = g_cat + (size_t)v * NCAT;
    const float* ag = g_agg + (size_t)v * AGGC;

    // agg row + self-loop term
#pragma unroll
    for (int j = 0; j < 2; j++) {
        int i = tid + j * 128;
        sagg[i] = ag[i] + oc[i] * d2;
    }
    if (tid < WCOMB) sw[tid] = oc[AGGC + tid] + b_comb[tid];
    __syncthreads();

    float val[4];
    float s = 0.f, sq = 0.f;
#pragma unroll
    for (int j = 0; j < 4; j++) {
        int c = tid + j * 128;
        int h = c >> 6, f = c & 63;
        const float* wv = &sw[h * 4];
        float a = wv[0] * sagg[f]
                + wv[1] * sagg[64 + f]
                + wv[2] * sagg[128 + f]
                + wv[3] * sagg[192 + f];
        a += conv_bias[c] + oc[AGGC + WCOMB + c] + b_res[c];
        val[j] = a;
        s += a;
        sq += a * a;
    }
#pragma unroll
    for (int o = 16; o > 0; o >>= 1) {
        s  += __shfl_xor_sync(0xffffffffu, s, o);
        sq += __shfl_xor_sync(0xffffffffu, sq, o);
    }
    if ((tid & 31) == 0) { red[tid >> 5] = s; red[4 + (tid >> 5)] = sq; }
    __syncthreads();
    s  = red[0] + red[1] + red[2] + red[3];
    sq = red[4] + red[5] + red[6] + red[7];
    float mean = s * (1.f / OUTF);
    float var  = sq * (1.f / OUTF) - mean * mean;
    float rstd = rsqrtf(var + LNEPS);
#pragma unroll
    for (int j = 0; j < 4; j++) {
        int c = tid + j * 128;
        float o = (val[j] - mean) * rstd * gamma[c] + beta[c];
        out[(size_t)v * OUTF + c] = fmaxf(o, 0.f);
    }
}

extern "C" void kernel_launch(void* const* d_in, const int* in_sizes, int n_in,
                              void* d_out, int out_size) {
    const float* x     = (const float*)d_in[0];
    const int*   ei    = (const int*)  d_in[1];
    const float* Wb    = (const float*)d_in[2];
    const float* Wc    = (const float*)d_in[3];
    const float* bcomb = (const float*)d_in[4];
    const float* cbias = (const float*)d_in[5];
    const float* Wr    = (const float*)d_in[6];
    const float* bres  = (const float*)d_in[7];
    const float* gamma = (const float*)d_in[8];
    const float* beta  = (const float*)d_in[9];
    float* out = (float*)d_out;

    const int N = in_sizes[0] / INF;
    const int E = in_sizes[1] / 2;

    // 1. zero agg + deg
    {
        int nAgg4 = (N * AGGC) / 4;
        int blocks = (nAgg4 + 255) / 256;
        zero_kernel<<<blocks, 256>>>(nAgg4, N);
    }
    // 2. concat + transpose weights
    concatw_kernel<<<(INF * NCAT + 255) / 256, 256>>>(Wb, Wc, Wr);
    // 3. degrees
    deg_kernel<<<(E + 255) / 256, 256>>>(ei, E);
    dinv_kernel<<<(N + 255) / 256, 256>>>(N);
    // 4. fused GEMM (FP16 tensor cores, fp32 accum, double-buffered): g_cat = x @ W
    {
        dim3 grid((NCAT + GBN - 1) / GBN, (N + GBM - 1) / GBM);
        f16gemm_kernel<<<grid, 256>>>(x, N);
    }
    // 5. edge scatter with vectorized reduction atomics
    {
        long long threads = (long long)E * 32;
        int blocks = (int)((threads + 255) / 256);
        scatter_kernel<<<blocks, 256>>>(ei, E);
    }
    // 6. combine + LayerNorm + ReLU
    combine_kernel<<<N, 128>>>(bcomb, cbias, bres, gamma, beta, out);
}